// round 4
// baseline (speedup 1.0000x reference)
#include <cuda_runtime.h>
#include <math.h>

#define N_ATOMS 10000
#define N_EDGES 160000
#define NSPEC   8
#define NSTRUCT 8
#define CH      16
#define NMAX    4
#define NBASIS  8
#define LMAXV   3
#define KTOT    256
#define CUTOFF  5.0f
#define PI_F    3.14159265358979f

// ---------------- device scratch ----------------
__device__ float g_U[(size_t)N_EDGES * 64];    // 40.96 MB, CSR: U[pos*64 + 4*(l*l+m) + n]
__device__ float g_hg[(size_t)N_EDGES * CH];   // 10.24 MB, staged h[sender] per CSR slot
__device__ int   g_send[N_EDGES];
__device__ float g_cemb[N_ATOMS * CH];
__device__ float g_h1[N_ATOMS * CH];
__device__ int   g_deg[N_ATOMS];
__device__ int   g_off[N_ATOMS];
__device__ int   g_cursor[N_ATOMS];

// ---------------- init ----------------
__global__ void k_init(const float* __restrict__ embed, const int* __restrict__ species,
                       float* __restrict__ out) {
    int i = blockIdx.x * blockDim.x + threadIdx.x;
    if (i < N_ATOMS * CH) g_cemb[i] = embed[species[i >> 4] * CH + (i & 15)];
    if (i < N_ATOMS) g_deg[i] = 0;
    if (i < NSTRUCT) out[i] = 0.f;
}

// ---------------- receiver histogram ----------------
__global__ void k_hist(const int* __restrict__ recv) {
    int e = blockIdx.x * blockDim.x + threadIdx.x;
    if (e < N_EDGES) atomicAdd(&g_deg[recv[e]], 1);
}

// ---------------- exclusive scan (single block, shfl) ----------------
__global__ void __launch_bounds__(1024) k_scan() {
    const int CHUNK = 10;
    int t = threadIdx.x;
    int lane = t & 31, warp = t >> 5;
    int start = t * CHUNK;

    int v[CHUNK];
    int s = 0;
#pragma unroll
    for (int i = 0; i < CHUNK; i++) {
        int idx = start + i;
        v[i] = (idx < N_ATOMS) ? g_deg[idx] : 0;
        s += v[i];
    }
    int x = s;
#pragma unroll
    for (int o = 1; o < 32; o <<= 1) {
        int y = __shfl_up_sync(0xFFFFFFFFu, x, o);
        if (lane >= o) x += y;
    }
    __shared__ int ws[32];
    if (lane == 31) ws[warp] = x;
    __syncthreads();
    if (warp == 0) {
        int wv = ws[lane];
#pragma unroll
        for (int o = 1; o < 32; o <<= 1) {
            int y = __shfl_up_sync(0xFFFFFFFFu, wv, o);
            if (lane >= o) wv += y;
        }
        ws[lane] = wv;
    }
    __syncthreads();
    int run = x - s + ((warp > 0) ? ws[warp - 1] : 0);
#pragma unroll
    for (int i = 0; i < CHUNK; i++) {
        int idx = start + i;
        if (idx < N_ATOMS) { g_off[idx] = run; g_cursor[idx] = run; }
        run += v[i];
    }
}

// ---------------- per-edge: sh x radial -> U at CSR slot; stage cemb[sender] ----------------
__global__ void k_edges(const float* __restrict__ pos,
                        const int* __restrict__ senders,
                        const int* __restrict__ recv,
                        const float* __restrict__ W_rad) {
    __shared__ float wrad[(LMAXV + 1) * NBASIS * NMAX];
    if (threadIdx.x < (LMAXV + 1) * NBASIS * NMAX) wrad[threadIdx.x] = W_rad[threadIdx.x];
    __syncthreads();

    int e = blockIdx.x * blockDim.x + threadIdx.x;
    if (e >= N_EDGES) return;
    int s = senders[e], r = recv[e];
    float dx = pos[r * 3 + 0] - pos[s * 3 + 0];
    float dy = pos[r * 3 + 1] - pos[s * 3 + 1];
    float dz = pos[r * 3 + 2] - pos[s * 3 + 2];
    float rn = sqrtf(dx * dx + dy * dy + dz * dz);
    float inv_u = __frcp_rn(fmaxf(rn, 1e-6f));
    float x = dx * inv_u, y = dy * inv_u, z = dz * inv_u;
    float x2 = x * x, y2 = y * y, z2 = z * z;

    float sh[16];
    sh[0]  = 0.28209479f;
    sh[1]  = 0.48860251f * y;
    sh[2]  = 0.48860251f * z;
    sh[3]  = 0.48860251f * x;
    sh[4]  = 1.09254843f * x * y;
    sh[5]  = 1.09254843f * y * z;
    sh[6]  = 0.31539157f * (3.0f * z2 - 1.0f);
    sh[7]  = 1.09254843f * x * z;
    sh[8]  = 0.54627422f * (x2 - y2);
    sh[9]  = 0.59004359f * y * (3.0f * x2 - y2);
    sh[10] = 2.89061144f * x * y * z;
    sh[11] = 0.45704579f * y * (5.0f * z2 - 1.0f);
    sh[12] = 0.37317633f * z * (5.0f * z2 - 3.0f);
    sh[13] = 0.45704579f * x * (5.0f * z2 - 1.0f);
    sh[14] = 1.44530572f * z * (x2 - y2);
    sh[15] = 0.59004359f * x * (x2 - 3.0f * y2);

    // radial: one ACCURATE sincos, then rotation recurrence (error ~n ulp, stable)
    float rr = fmaxf(rn, 1e-6f);
    float theta = PI_F * (1.0f / CUTOFF) * rr;     // up to ~3.27
    float s1, c1;
    sincosf(theta, &s1, &c1);
    // cutoff: cos(min(theta,pi)) == (theta < pi) ? c1 : -1
    float fc = (theta < PI_F) ? 0.5f * (c1 + 1.0f) : 0.0f;
    float pref = 0.63245553f * inv_u * fc;          // sqrt(2/CUTOFF)/rr * fc
    float bf[NBASIS];
    {
        float sk = s1, ck = c1;                     // sin(kθ), cos(kθ), k=1
        bf[0] = pref * sk;
#pragma unroll
        for (int n = 1; n < NBASIS; n++) {
            float sn = fmaf(sk, c1, ck * s1);       // sin((k+1)θ)
            float cn = fmaf(ck, c1, -sk * s1);      // cos((k+1)θ)
            sk = sn; ck = cn;
            bf[n] = pref * sk;
        }
    }

    float R[LMAXV + 1][NMAX];
#pragma unroll
    for (int l = 0; l <= LMAXV; l++) {
#pragma unroll
        for (int n = 0; n < NMAX; n++) {
            float acc = 0.f;
#pragma unroll
            for (int b = 0; b < NBASIS; b++)
                acc += bf[b] * wrad[l * (NBASIS * NMAX) + b * NMAX + n];
            R[l][n] = acc;
        }
    }

    int posn = atomicAdd(&g_cursor[r], 1);
    g_send[posn] = s;

    // stage layer-1 h (= cemb[sender]) at CSR slot
    {
        const float4* src = (const float4*)&g_cemb[s * CH];
        float4* dst = (float4*)&g_hg[(size_t)posn * CH];
        dst[0] = src[0]; dst[1] = src[1]; dst[2] = src[2]; dst[3] = src[3];
    }

    float4* U4 = (float4*)(&g_U[(size_t)posn * 64]);
    int q = 0;
#pragma unroll
    for (int l = 0; l <= LMAXV; l++) {
#pragma unroll
        for (int m = 0; m < 2 * LMAXV + 1; m++) {
            if (m < 2 * l + 1) {
                float sv = sh[l * l + m];
                U4[q++] = make_float4(sv * R[l][0], sv * R[l][1], sv * R[l][2], sv * R[l][3]);
            }
        }
    }
}

// ---------------- stage h1[sender] per CSR slot (for layer 2) ----------------
__global__ void k_gather() {
    int i = blockIdx.x * blockDim.x + threadIdx.x;   // one float4 each
    if (i < N_EDGES * 4) {
        int posn = i >> 2, q = i & 3;
        int snd = g_send[posn];
        ((float4*)g_hg)[(size_t)posn * 4 + q] = ((const float4*)g_h1)[snd * 4 + q];
    }
}

// ---------------- per-atom: streaming A accumulation + CG invariants ----------------
template<bool FINAL>
__global__ void __launch_bounds__(256) k_layer(
    const float* __restrict__ W,       // W_inv (non-final)
    const float* __restrict__ w_out,   // final
    const float* __restrict__ comp_w,  // final
    const int* __restrict__ species,   // final
    const int* __restrict__ sid,       // final
    float* __restrict__ out)           // final
{
    int atom = blockIdx.x;
    int t = threadIdx.x;
    int sub = t >> 6;
    int tid = t & 63;
    int jg = tid & 15;
    int cg = tid >> 4;

    int off = g_off[atom];
    int cnt = g_deg[atom];

    float acc[16];
#pragma unroll
    for (int i = 0; i < 16; i++) acc[i] = 0.f;

    const float* Ub = &g_U[(size_t)off * 64 + 4 * jg];
    const float* Hb = &g_hg[(size_t)off * CH + 4 * cg];

    int k = sub;
    for (; k + 4 < cnt; k += 8) {
        float4 u0 = *(const float4*)(Ub + (size_t)k * 64);
        float4 h0 = *(const float4*)(Hb + (size_t)k * CH);
        float4 u1 = *(const float4*)(Ub + (size_t)(k + 4) * 64);
        float4 h1 = *(const float4*)(Hb + (size_t)(k + 4) * CH);
        acc[0]  = fmaf(u0.x, h0.x, acc[0]);  acc[1]  = fmaf(u0.x, h0.y, acc[1]);
        acc[2]  = fmaf(u0.x, h0.z, acc[2]);  acc[3]  = fmaf(u0.x, h0.w, acc[3]);
        acc[4]  = fmaf(u0.y, h0.x, acc[4]);  acc[5]  = fmaf(u0.y, h0.y, acc[5]);
        acc[6]  = fmaf(u0.y, h0.z, acc[6]);  acc[7]  = fmaf(u0.y, h0.w, acc[7]);
        acc[8]  = fmaf(u0.z, h0.x, acc[8]);  acc[9]  = fmaf(u0.z, h0.y, acc[9]);
        acc[10] = fmaf(u0.z, h0.z, acc[10]); acc[11] = fmaf(u0.z, h0.w, acc[11]);
        acc[12] = fmaf(u0.w, h0.x, acc[12]); acc[13] = fmaf(u0.w, h0.y, acc[13]);
        acc[14] = fmaf(u0.w, h0.z, acc[14]); acc[15] = fmaf(u0.w, h0.w, acc[15]);
        acc[0]  = fmaf(u1.x, h1.x, acc[0]);  acc[1]  = fmaf(u1.x, h1.y, acc[1]);
        acc[2]  = fmaf(u1.x, h1.z, acc[2]);  acc[3]  = fmaf(u1.x, h1.w, acc[3]);
        acc[4]  = fmaf(u1.y, h1.x, acc[4]);  acc[5]  = fmaf(u1.y, h1.y, acc[5]);
        acc[6]  = fmaf(u1.y, h1.z, acc[6]);  acc[7]  = fmaf(u1.y, h1.w, acc[7]);
        acc[8]  = fmaf(u1.z, h1.x, acc[8]);  acc[9]  = fmaf(u1.z, h1.y, acc[9]);
        acc[10] = fmaf(u1.z, h1.z, acc[10]); acc[11] = fmaf(u1.z, h1.w, acc[11]);
        acc[12] = fmaf(u1.w, h1.x, acc[12]); acc[13] = fmaf(u1.w, h1.y, acc[13]);
        acc[14] = fmaf(u1.w, h1.z, acc[14]); acc[15] = fmaf(u1.w, h1.w, acc[15]);
    }
    for (; k < cnt; k += 4) {
        float4 u = *(const float4*)(Ub + (size_t)k * 64);
        float4 h = *(const float4*)(Hb + (size_t)k * CH);
        acc[0]  = fmaf(u.x, h.x, acc[0]);  acc[1]  = fmaf(u.x, h.y, acc[1]);
        acc[2]  = fmaf(u.x, h.z, acc[2]);  acc[3]  = fmaf(u.x, h.w, acc[3]);
        acc[4]  = fmaf(u.y, h.x, acc[4]);  acc[5]  = fmaf(u.y, h.y, acc[5]);
        acc[6]  = fmaf(u.y, h.z, acc[6]);  acc[7]  = fmaf(u.y, h.w, acc[7]);
        acc[8]  = fmaf(u.z, h.x, acc[8]);  acc[9]  = fmaf(u.z, h.y, acc[9]);
        acc[10] = fmaf(u.z, h.z, acc[10]); acc[11] = fmaf(u.z, h.w, acc[11]);
        acc[12] = fmaf(u.w, h.x, acc[12]); acc[13] = fmaf(u.w, h.y, acc[13]);
        acc[14] = fmaf(u.w, h.z, acc[14]); acc[15] = fmaf(u.w, h.w, acc[15]);
    }

    __shared__ float As[4][64][17];
    __shared__ float invs[KTOT];
#pragma unroll
    for (int a = 0; a < 4; a++)
#pragma unroll
        for (int b = 0; b < 4; b++)
            As[sub][4 * jg + a][4 * cg + b] = acc[a * 4 + b];
    __syncthreads();

    {
        int l = t >> 6;
        int n = (t >> 4) & 3;
        int c = t & 15;
        int base = 4 * l * l;
        float s2 = 0.f;
        for (int m = 0; m < 2 * l + 1; m++) {
            int j = base + 4 * m + n;
            float a = As[0][j][c] + As[1][j][c] + As[2][j][c] + As[3][j][c];
            s2 = fmaf(a, a, s2);
        }
        invs[t] = s2 * rsqrtf(2.0f * (float)l + 1.0f);
    }
    __syncthreads();

    if (FINAL) {
        __shared__ float rd[256];
        rd[t] = invs[t] * w_out[t];
        __syncthreads();
        for (int sred = 128; sred > 0; sred >>= 1) {
            if (t < sred) rd[t] += rd[t + sred];
            __syncthreads();
        }
        if (t == 0)
            atomicAdd(&out[sid[atom]], rd[0] + comp_w[species[atom]]);
    } else {
        __shared__ float red[16 * 17];
        int cp = t & 15, chunk = t >> 4;
        float p = 0.f;
#pragma unroll
        for (int q = 0; q < 16; q++) {
            int jj = chunk * 16 + q;
            p = fmaf(invs[jj], W[jj * CH + cp], p);
        }
        red[chunk * 17 + cp] = p;
        __syncthreads();
        if (t < CH) {
            float sfin = 0.f;
#pragma unroll
            for (int ch = 0; ch < 16; ch++) sfin += red[ch * 17 + t];
            g_h1[atom * CH + t] = sfin * g_cemb[atom * CH + t];
        }
    }
}

// ---------------- launch ----------------
extern "C" void kernel_launch(void* const* d_in, const int* in_sizes, int n_in,
                              void* d_out, int out_size) {
    const float* positions  = (const float*)d_in[0];
    const float* embed      = (const float*)d_in[1];
    const float* W_rad      = (const float*)d_in[2];
    const float* W_inv1     = (const float*)d_in[3];
    // d_in[4] = W_inv2 is dead: reference returns inv2 before applying it
    const float* w_out      = (const float*)d_in[5];
    const float* comp_w     = (const float*)d_in[6];
    const int*   senders    = (const int*)d_in[7];
    const int*   receivers  = (const int*)d_in[8];
    const int*   species    = (const int*)d_in[9];
    const int*   struct_ids = (const int*)d_in[10];
    float* out = (float*)d_out;

    k_init<<<(N_ATOMS * CH + 255) / 256, 256>>>(embed, species, out);
    k_hist<<<(N_EDGES + 255) / 256, 256>>>(receivers);
    k_scan<<<1, 1024>>>();
    k_edges<<<(N_EDGES + 255) / 256, 256>>>(positions, senders, receivers, W_rad);

    k_layer<false><<<N_ATOMS, 256>>>(W_inv1, nullptr, nullptr, nullptr, nullptr, nullptr);
    k_gather<<<(N_EDGES * 4 + 255) / 256, 256>>>();
    k_layer<true><<<N_ATOMS, 256>>>(nullptr, w_out, comp_w, species, struct_ids, out);
}

// round 5
// speedup vs baseline: 1.4085x; 1.4085x over previous
#include <cuda_runtime.h>
#include <math.h>

#define N_ATOMS 10000
#define N_EDGES 160000
#define NSPEC   8
#define NSTRUCT 8
#define CH      16
#define NMAX    4
#define NBASIS  8
#define LMAXV   3
#define KTOT    256
#define CUTOFF  5.0f
#define PI_F    3.14159265358979f

// ---------------- device scratch ----------------
__device__ float g_sh[(size_t)N_EDGES * 16];   // 10.24 MB, CSR order
__device__ float g_R [(size_t)N_EDGES * 16];   // 10.24 MB, CSR order (l,n)
__device__ int   g_send[N_EDGES];              // sender per CSR slot
__device__ int   g_pos[N_EDGES];               // edge -> CSR slot
__device__ float g_cemb[N_ATOMS * CH];
__device__ float g_h1[N_ATOMS * CH];
__device__ int   g_deg[N_ATOMS];
__device__ int   g_off[N_ATOMS];
__device__ int   g_cursor[N_ATOMS];

// ---------------- init ----------------
__global__ void k_init(const float* __restrict__ embed, const int* __restrict__ species,
                       float* __restrict__ out) {
    int i = blockIdx.x * blockDim.x + threadIdx.x;
    if (i < N_ATOMS * CH) g_cemb[i] = embed[species[i >> 4] * CH + (i & 15)];
    if (i < N_ATOMS) g_deg[i] = 0;
    if (i < NSTRUCT) out[i] = 0.f;
}

// ---------------- receiver histogram ----------------
__global__ void k_hist(const int* __restrict__ recv) {
    int e = blockIdx.x * blockDim.x + threadIdx.x;
    if (e < N_EDGES) atomicAdd(&g_deg[recv[e]], 1);
}

// ---------------- exclusive scan (single block, shfl) ----------------
__global__ void __launch_bounds__(1024) k_scan() {
    const int CHUNK = 10;
    int t = threadIdx.x;
    int lane = t & 31, warp = t >> 5;
    int start = t * CHUNK;

    int v[CHUNK];
    int s = 0;
#pragma unroll
    for (int i = 0; i < CHUNK; i++) {
        int idx = start + i;
        v[i] = (idx < N_ATOMS) ? g_deg[idx] : 0;
        s += v[i];
    }
    int x = s;
#pragma unroll
    for (int o = 1; o < 32; o <<= 1) {
        int y = __shfl_up_sync(0xFFFFFFFFu, x, o);
        if (lane >= o) x += y;
    }
    __shared__ int ws[32];
    if (lane == 31) ws[warp] = x;
    __syncthreads();
    if (warp == 0) {
        int wv = ws[lane];
#pragma unroll
        for (int o = 1; o < 32; o <<= 1) {
            int y = __shfl_up_sync(0xFFFFFFFFu, wv, o);
            if (lane >= o) wv += y;
        }
        ws[lane] = wv;
    }
    __syncthreads();
    int run = x - s + ((warp > 0) ? ws[warp - 1] : 0);
#pragma unroll
    for (int i = 0; i < CHUNK; i++) {
        int idx = start + i;
        if (idx < N_ATOMS) { g_off[idx] = run; g_cursor[idx] = run; }
        run += v[i];
    }
}

// ---------------- slot assignment (isolates the atomic) ----------------
__global__ void k_slot(const int* __restrict__ senders, const int* __restrict__ recv) {
    int e = blockIdx.x * blockDim.x + threadIdx.x;
    if (e < N_EDGES) {
        int posn = atomicAdd(&g_cursor[recv[e]], 1);
        g_pos[e] = posn;
        g_send[posn] = senders[e];
    }
}

// ---------------- per-edge: sh[16] + R[16] written at CSR slot ----------------
__global__ void k_edges(const float* __restrict__ pos,
                        const int* __restrict__ senders,
                        const int* __restrict__ recv,
                        const float* __restrict__ W_rad) {
    __shared__ float wrad[(LMAXV + 1) * NBASIS * NMAX];
    if (threadIdx.x < (LMAXV + 1) * NBASIS * NMAX) wrad[threadIdx.x] = W_rad[threadIdx.x];
    __syncthreads();

    int e = blockIdx.x * blockDim.x + threadIdx.x;
    if (e >= N_EDGES) return;
    int posn = g_pos[e];           // early independent load
    int s = senders[e], r = recv[e];
    float dx = pos[r * 3 + 0] - pos[s * 3 + 0];
    float dy = pos[r * 3 + 1] - pos[s * 3 + 1];
    float dz = pos[r * 3 + 2] - pos[s * 3 + 2];
    float rn = sqrtf(dx * dx + dy * dy + dz * dz);
    float inv_u = __frcp_rn(fmaxf(rn, 1e-6f));
    float x = dx * inv_u, y = dy * inv_u, z = dz * inv_u;
    float x2 = x * x, y2 = y * y, z2 = z * z;

    float sh[16];
    sh[0]  = 0.28209479f;
    sh[1]  = 0.48860251f * y;
    sh[2]  = 0.48860251f * z;
    sh[3]  = 0.48860251f * x;
    sh[4]  = 1.09254843f * x * y;
    sh[5]  = 1.09254843f * y * z;
    sh[6]  = 0.31539157f * (3.0f * z2 - 1.0f);
    sh[7]  = 1.09254843f * x * z;
    sh[8]  = 0.54627422f * (x2 - y2);
    sh[9]  = 0.59004359f * y * (3.0f * x2 - y2);
    sh[10] = 2.89061144f * x * y * z;
    sh[11] = 0.45704579f * y * (5.0f * z2 - 1.0f);
    sh[12] = 0.37317633f * z * (5.0f * z2 - 3.0f);
    sh[13] = 0.45704579f * x * (5.0f * z2 - 1.0f);
    sh[14] = 1.44530572f * z * (x2 - y2);
    sh[15] = 0.59004359f * x * (x2 - 3.0f * y2);

    // accurate sincos once, stable rotation recurrence
    float rr = fmaxf(rn, 1e-6f);
    float theta = PI_F * (1.0f / CUTOFF) * rr;
    float s1, c1;
    sincosf(theta, &s1, &c1);
    float fc = (theta < PI_F) ? 0.5f * (c1 + 1.0f) : 0.0f;
    float pref = 0.63245553f * inv_u * fc;
    float bf[NBASIS];
    {
        float sk = s1, ck = c1;
        bf[0] = pref * sk;
#pragma unroll
        for (int n = 1; n < NBASIS; n++) {
            float sn = fmaf(sk, c1, ck * s1);
            float cn = fmaf(ck, c1, -sk * s1);
            sk = sn; ck = cn;
            bf[n] = pref * sk;
        }
    }

    float4 Rq[LMAXV + 1];
#pragma unroll
    for (int l = 0; l <= LMAXV; l++) {
        float a0 = 0.f, a1 = 0.f, a2 = 0.f, a3 = 0.f;
#pragma unroll
        for (int b = 0; b < NBASIS; b++) {
            const float* wl = &wrad[l * (NBASIS * NMAX) + b * NMAX];
            a0 = fmaf(bf[b], wl[0], a0);
            a1 = fmaf(bf[b], wl[1], a1);
            a2 = fmaf(bf[b], wl[2], a2);
            a3 = fmaf(bf[b], wl[3], a3);
        }
        Rq[l] = make_float4(a0, a1, a2, a3);
    }

    float4* SH4 = (float4*)&g_sh[(size_t)posn * 16];
    SH4[0] = make_float4(sh[0],  sh[1],  sh[2],  sh[3]);
    SH4[1] = make_float4(sh[4],  sh[5],  sh[6],  sh[7]);
    SH4[2] = make_float4(sh[8],  sh[9],  sh[10], sh[11]);
    SH4[3] = make_float4(sh[12], sh[13], sh[14], sh[15]);
    float4* R4p = (float4*)&g_R[(size_t)posn * 16];
    R4p[0] = Rq[0]; R4p[1] = Rq[1]; R4p[2] = Rq[2]; R4p[3] = Rq[3];
}

// ---------------- warp-per-atom layer: gather + CG invariants ----------------
// lane: jg = lane&15 owns m-index (jg = l*l+m), n=0..3 via R components;
// ch = lane>>4 owns channels c = 8*ch..8*ch+7. acc[4][8] registers.
template<bool FINAL>
__global__ void __launch_bounds__(128) k_layer(
    int use_h1,
    const float* __restrict__ W,       // W_inv (non-final)
    const float* __restrict__ w_out,   // final
    const float* __restrict__ comp_w,  // final
    const int* __restrict__ species,   // final
    const int* __restrict__ sid,       // final
    float* __restrict__ out)           // final
{
    const float* __restrict__ h_in = use_h1 ? g_h1 : g_cemb;
    int warp = threadIdx.x >> 5, lane = threadIdx.x & 31;
    int atom = (blockIdx.x << 2) + warp;
    int jg = lane & 15, ch = lane >> 4;
    int l = (jg == 0) ? 0 : (jg < 4) ? 1 : (jg < 9) ? 2 : 3;

    __shared__ float smA[4][16 * 4 * 17];   // [(jg*4+n)*17 + c]
    __shared__ float sminv[4][KTOT];

    int off = g_off[atom];
    int cnt = g_deg[atom];

    float acc[4][8];
#pragma unroll
    for (int n = 0; n < 4; n++)
#pragma unroll
        for (int cc = 0; cc < 8; cc++) acc[n][cc] = 0.f;

    const float* shp = g_sh + (size_t)off * 16 + jg;
    const float* Rp  = g_R  + (size_t)off * 16 + 4 * l;
    const int*   sp  = g_send + off;
    const float4* h4 = (const float4*)h_in;

    int snd = (cnt > 0) ? sp[0] : 0;
    for (int k = 0; k < cnt; k++) {
        int scur = snd;
        if (k + 1 < cnt) snd = sp[k + 1];        // prefetch next sender
        float  shv = shp[(size_t)k * 16];
        float4 R4  = *(const float4*)(Rp + (size_t)k * 16);
        float4 ha  = h4[scur * 4 + 2 * ch];
        float4 hb  = h4[scur * 4 + 2 * ch + 1];
        float u0 = shv * R4.x, u1 = shv * R4.y, u2 = shv * R4.z, u3 = shv * R4.w;
#define ACCROW(n, u) \
        acc[n][0] = fmaf(u, ha.x, acc[n][0]); acc[n][1] = fmaf(u, ha.y, acc[n][1]); \
        acc[n][2] = fmaf(u, ha.z, acc[n][2]); acc[n][3] = fmaf(u, ha.w, acc[n][3]); \
        acc[n][4] = fmaf(u, hb.x, acc[n][4]); acc[n][5] = fmaf(u, hb.y, acc[n][5]); \
        acc[n][6] = fmaf(u, hb.z, acc[n][6]); acc[n][7] = fmaf(u, hb.w, acc[n][7]);
        ACCROW(0, u0) ACCROW(1, u1) ACCROW(2, u2) ACCROW(3, u3)
#undef ACCROW
    }

    // write squared A to warp-private smem: each (j,c) owned by exactly one lane
    float* sA = smA[warp];
#pragma unroll
    for (int n = 0; n < 4; n++)
#pragma unroll
        for (int cc = 0; cc < 8; cc++) {
            float a = acc[n][cc];
            sA[(jg * 4 + n) * 17 + 8 * ch + cc] = a * a;
        }
    __syncwarp();

    // inv[idx], idx = l*64 + n*16 + c; 8 entries per lane
    float inv[8];
#pragma unroll
    for (int q = 0; q < 8; q++) {
        int idx = lane * 8 + q;
        int li = idx >> 6, ni = (idx >> 4) & 3, ci = idx & 15;
        int base = li * li;
        float sacc = 0.f;
        for (int m = 0; m <= 2 * li; m++)
            sacc += sA[((base + m) * 4 + ni) * 17 + ci];
        inv[q] = sacc * rsqrtf(2.0f * (float)li + 1.0f);
    }

    if (FINAL) {
        float part = 0.f;
#pragma unroll
        for (int q = 0; q < 8; q++)
            part = fmaf(inv[q], w_out[lane * 8 + q], part);
#pragma unroll
        for (int o = 16; o > 0; o >>= 1)
            part += __shfl_down_sync(0xFFFFFFFFu, part, o);
        if (lane == 0)
            atomicAdd(&out[sid[atom]], part + comp_w[species[atom]]);
    } else {
        float* sv = sminv[warp];
#pragma unroll
        for (int q = 0; q < 8; q++) sv[lane * 8 + q] = inv[q];
        __syncwarp();
        int cp = lane & 15, half = lane >> 4;
        float p0 = 0.f, p1 = 0.f;
#pragma unroll 8
        for (int i = 0; i < 128; i += 2) {
            int jj = (half << 7) + i;
            p0 = fmaf(sv[jj],     W[jj * 16 + cp],        p0);
            p1 = fmaf(sv[jj + 1], W[(jj + 1) * 16 + cp],  p1);
        }
        float p = p0 + p1;
        p += __shfl_down_sync(0xFFFFFFFFu, p, 16);
        if (lane < 16)
            g_h1[atom * CH + lane] = p * g_cemb[atom * CH + lane];
    }
}

// ---------------- launch ----------------
extern "C" void kernel_launch(void* const* d_in, const int* in_sizes, int n_in,
                              void* d_out, int out_size) {
    const float* positions  = (const float*)d_in[0];
    const float* embed      = (const float*)d_in[1];
    const float* W_rad      = (const float*)d_in[2];
    const float* W_inv1     = (const float*)d_in[3];
    // d_in[4] = W_inv2 is dead: reference returns inv2 before applying it
    const float* w_out      = (const float*)d_in[5];
    const float* comp_w     = (const float*)d_in[6];
    const int*   senders    = (const int*)d_in[7];
    const int*   receivers  = (const int*)d_in[8];
    const int*   species    = (const int*)d_in[9];
    const int*   struct_ids = (const int*)d_in[10];
    float* out = (float*)d_out;

    k_init<<<(N_ATOMS * CH + 255) / 256, 256>>>(embed, species, out);
    k_hist<<<(N_EDGES + 255) / 256, 256>>>(receivers);
    k_scan<<<1, 1024>>>();
    k_slot<<<(N_EDGES + 255) / 256, 256>>>(senders, receivers);
    k_edges<<<(N_EDGES + 255) / 256, 256>>>(positions, senders, receivers, W_rad);

    k_layer<false><<<N_ATOMS / 4, 128>>>(0, W_inv1, nullptr, nullptr, nullptr, nullptr, nullptr);
    k_layer<true><<<N_ATOMS / 4, 128>>>(1, nullptr, w_out, comp_w, species, struct_ids, out);
}

// round 7
// speedup vs baseline: 1.6376x; 1.1627x over previous
#include <cuda_runtime.h>
#include <math.h>

#define N_ATOMS 10000
#define N_EDGES 160000
#define NSPEC   8
#define NSTRUCT 8
#define CH      16
#define NMAX    4
#define NBASIS  8
#define LMAXV   3
#define KTOT    256
#define CUTOFF  5.0f
#define PI_F    3.14159265358979f

// ---------------- device scratch ----------------
__device__ float g_sh[(size_t)N_EDGES * 16];   // CSR order
__device__ float g_R [(size_t)N_EDGES * 16];   // CSR order (l,n)
__device__ int   g_send[N_EDGES];              // sender per CSR slot
__device__ int   g_rank[N_EDGES];              // edge -> rank within receiver segment
__device__ float g_cemb[N_ATOMS * CH];
__device__ float g_h1[N_ATOMS * CH];
__device__ int   g_deg[N_ATOMS];
__device__ int   g_off[N_ATOMS];

// ---------------- init ----------------
__global__ void k_init(const float* __restrict__ embed, const int* __restrict__ species,
                       float* __restrict__ out) {
    int i = blockIdx.x * blockDim.x + threadIdx.x;
    if (i < N_ATOMS * CH) g_cemb[i] = embed[species[i >> 4] * CH + (i & 15)];
    if (i < N_ATOMS) g_deg[i] = 0;
    if (i < NSTRUCT) out[i] = 0.f;
}

// ---------------- receiver histogram + per-edge rank (one atomic pass) ----------------
__global__ void k_hist(const int* __restrict__ recv) {
    int e = blockIdx.x * blockDim.x + threadIdx.x;
    if (e < N_EDGES) g_rank[e] = atomicAdd(&g_deg[recv[e]], 1);
}

// ---------------- exclusive scan (single block, shfl) ----------------
__global__ void __launch_bounds__(1024) k_scan() {
    const int CHUNK = 10;
    int t = threadIdx.x;
    int lane = t & 31, warp = t >> 5;
    int start = t * CHUNK;

    int v[CHUNK];
    int s = 0;
#pragma unroll
    for (int i = 0; i < CHUNK; i++) {
        int idx = start + i;
        v[i] = (idx < N_ATOMS) ? g_deg[idx] : 0;
        s += v[i];
    }
    int x = s;
#pragma unroll
    for (int o = 1; o < 32; o <<= 1) {
        int y = __shfl_up_sync(0xFFFFFFFFu, x, o);
        if (lane >= o) x += y;
    }
    __shared__ int ws[32];
    if (lane == 31) ws[warp] = x;
    __syncthreads();
    if (warp == 0) {
        int wv = ws[lane];
#pragma unroll
        for (int o = 1; o < 32; o <<= 1) {
            int y = __shfl_up_sync(0xFFFFFFFFu, wv, o);
            if (lane >= o) wv += y;
        }
        ws[lane] = wv;
    }
    __syncthreads();
    int run = x - s + ((warp > 0) ? ws[warp - 1] : 0);
#pragma unroll
    for (int i = 0; i < CHUNK; i++) {
        int idx = start + i;
        if (idx < N_ATOMS) g_off[idx] = run;
        run += v[i];
    }
}

// ---------------- per-edge: sh[16] + R[16] written at CSR slot ----------------
__global__ void k_edges(const float* __restrict__ pos,
                        const int* __restrict__ senders,
                        const int* __restrict__ recv,
                        const float* __restrict__ W_rad) {
    __shared__ float wrad[(LMAXV + 1) * NBASIS * NMAX];
    if (threadIdx.x < (LMAXV + 1) * NBASIS * NMAX) wrad[threadIdx.x] = W_rad[threadIdx.x];
    __syncthreads();

    int e = blockIdx.x * blockDim.x + threadIdx.x;
    if (e >= N_EDGES) return;
    int s = senders[e], r = recv[e];
    int posn = g_off[r] + g_rank[e];
    float dx = pos[r * 3 + 0] - pos[s * 3 + 0];
    float dy = pos[r * 3 + 1] - pos[s * 3 + 1];
    float dz = pos[r * 3 + 2] - pos[s * 3 + 2];
    float rn = sqrtf(dx * dx + dy * dy + dz * dz);
    float inv_u = __frcp_rn(fmaxf(rn, 1e-6f));
    float x = dx * inv_u, y = dy * inv_u, z = dz * inv_u;
    float x2 = x * x, y2 = y * y, z2 = z * z;

    float sh[16];
    sh[0]  = 0.28209479f;
    sh[1]  = 0.48860251f * y;
    sh[2]  = 0.48860251f * z;
    sh[3]  = 0.48860251f * x;
    sh[4]  = 1.09254843f * x * y;
    sh[5]  = 1.09254843f * y * z;
    sh[6]  = 0.31539157f * (3.0f * z2 - 1.0f);
    sh[7]  = 1.09254843f * x * z;
    sh[8]  = 0.54627422f * (x2 - y2);
    sh[9]  = 0.59004359f * y * (3.0f * x2 - y2);
    sh[10] = 2.89061144f * x * y * z;
    sh[11] = 0.45704579f * y * (5.0f * z2 - 1.0f);
    sh[12] = 0.37317633f * z * (5.0f * z2 - 3.0f);
    sh[13] = 0.45704579f * x * (5.0f * z2 - 1.0f);
    sh[14] = 1.44530572f * z * (x2 - y2);
    sh[15] = 0.59004359f * x * (x2 - 3.0f * y2);

    // accurate sincos once, stable rotation recurrence
    float rr = fmaxf(rn, 1e-6f);
    float theta = PI_F * (1.0f / CUTOFF) * rr;
    float s1, c1;
    sincosf(theta, &s1, &c1);
    float fc = (theta < PI_F) ? 0.5f * (c1 + 1.0f) : 0.0f;
    float pref = 0.63245553f * inv_u * fc;
    float bf[NBASIS];
    {
        float sk = s1, ck = c1;
        bf[0] = pref * sk;
#pragma unroll
        for (int n = 1; n < NBASIS; n++) {
            float sn = fmaf(sk, c1, ck * s1);
            float cn = fmaf(ck, c1, -sk * s1);
            sk = sn; ck = cn;
            bf[n] = pref * sk;
        }
    }

    float4 Rq[LMAXV + 1];
#pragma unroll
    for (int l = 0; l <= LMAXV; l++) {
        float a0 = 0.f, a1 = 0.f, a2 = 0.f, a3 = 0.f;
#pragma unroll
        for (int b = 0; b < NBASIS; b++) {
            const float* wl = &wrad[l * (NBASIS * NMAX) + b * NMAX];
            a0 = fmaf(bf[b], wl[0], a0);
            a1 = fmaf(bf[b], wl[1], a1);
            a2 = fmaf(bf[b], wl[2], a2);
            a3 = fmaf(bf[b], wl[3], a3);
        }
        Rq[l] = make_float4(a0, a1, a2, a3);
    }

    g_send[posn] = s;
    float4* SH4 = (float4*)&g_sh[(size_t)posn * 16];
    SH4[0] = make_float4(sh[0],  sh[1],  sh[2],  sh[3]);
    SH4[1] = make_float4(sh[4],  sh[5],  sh[6],  sh[7]);
    SH4[2] = make_float4(sh[8],  sh[9],  sh[10], sh[11]);
    SH4[3] = make_float4(sh[12], sh[13], sh[14], sh[15]);
    float4* R4p = (float4*)&g_R[(size_t)posn * 16];
    R4p[0] = Rq[0]; R4p[1] = Rq[1]; R4p[2] = Rq[2]; R4p[3] = Rq[3];
}

// ---------------- warp-per-atom layer: gather + CG invariants ----------------
// lane: jg = lane&15 owns m-index (jg = l*l+m); ch = lane>>4 owns c = 8ch..8ch+7.
// 2-edge software pipeline with sender prefetch.
template<bool FINAL>
__global__ void __launch_bounds__(128) k_layer(
    int use_h1,
    const float* __restrict__ W,       // W_inv (non-final)
    const float* __restrict__ w_out,   // final
    const float* __restrict__ comp_w,  // final
    const int* __restrict__ species,   // final
    const int* __restrict__ sid,       // final
    float* __restrict__ out)           // final
{
    const float* __restrict__ h_in = use_h1 ? g_h1 : g_cemb;
    int warp = threadIdx.x >> 5, lane = threadIdx.x & 31;
    int atom = (blockIdx.x << 2) + warp;
    int jg = lane & 15, ch2 = (lane >> 4) << 1;   // h float4 index offset
    int l = (jg == 0) ? 0 : (jg < 4) ? 1 : (jg < 9) ? 2 : 3;

    __shared__ float smA[4][16 * 4 * 17];
    __shared__ float sminv[4][KTOT];

    int off = g_off[atom];
    int cnt = g_deg[atom];

    float acc[4][8];
#pragma unroll
    for (int n = 0; n < 4; n++)
#pragma unroll
        for (int cc = 0; cc < 8; cc++) acc[n][cc] = 0.f;

    const float* shp = g_sh + (size_t)off * 16 + jg;
    const float* Rp  = g_R  + (size_t)off * 16 + 4 * l;
    const int*   sp  = g_send + off;
    const float4* h4 = (const float4*)h_in;

#define ACCROW(n, u, ha, hb) \
        acc[n][0] = fmaf(u, ha.x, acc[n][0]); acc[n][1] = fmaf(u, ha.y, acc[n][1]); \
        acc[n][2] = fmaf(u, ha.z, acc[n][2]); acc[n][3] = fmaf(u, ha.w, acc[n][3]); \
        acc[n][4] = fmaf(u, hb.x, acc[n][4]); acc[n][5] = fmaf(u, hb.y, acc[n][5]); \
        acc[n][6] = fmaf(u, hb.z, acc[n][6]); acc[n][7] = fmaf(u, hb.w, acc[n][7]);

    int s0 = (cnt > 0) ? sp[0] : 0;
    int s1 = (cnt > 1) ? sp[1] : 0;
    int k = 0;
    for (; k + 1 < cnt; k += 2) {
        // batch all loads for edge pair (k, k+1)
        float  shv0 = shp[(size_t)k * 16];
        float  shv1 = shp[(size_t)(k + 1) * 16];
        float4 R40  = *(const float4*)(Rp + (size_t)k * 16);
        float4 R41  = *(const float4*)(Rp + (size_t)(k + 1) * 16);
        float4 ha0  = h4[s0 * 4 + ch2];
        float4 hb0  = h4[s0 * 4 + ch2 + 1];
        float4 ha1  = h4[s1 * 4 + ch2];
        float4 hb1  = h4[s1 * 4 + ch2 + 1];
        // prefetch senders for next pair (slack = full FMA block below)
        if (k + 2 < cnt) s0 = sp[k + 2];
        if (k + 3 < cnt) s1 = sp[k + 3];

        float u0 = shv0 * R40.x, u1 = shv0 * R40.y, u2 = shv0 * R40.z, u3 = shv0 * R40.w;
        ACCROW(0, u0, ha0, hb0) ACCROW(1, u1, ha0, hb0)
        ACCROW(2, u2, ha0, hb0) ACCROW(3, u3, ha0, hb0)
        float v0 = shv1 * R41.x, v1 = shv1 * R41.y, v2 = shv1 * R41.z, v3 = shv1 * R41.w;
        ACCROW(0, v0, ha1, hb1) ACCROW(1, v1, ha1, hb1)
        ACCROW(2, v2, ha1, hb1) ACCROW(3, v3, ha1, hb1)
    }
    if (k < cnt) {   // odd tail (sender already prefetched into s0)
        float  shv = shp[(size_t)k * 16];
        float4 R4  = *(const float4*)(Rp + (size_t)k * 16);
        float4 ha  = h4[s0 * 4 + ch2];
        float4 hb  = h4[s0 * 4 + ch2 + 1];
        float u0 = shv * R4.x, u1 = shv * R4.y, u2 = shv * R4.z, u3 = shv * R4.w;
        ACCROW(0, u0, ha, hb) ACCROW(1, u1, ha, hb)
        ACCROW(2, u2, ha, hb) ACCROW(3, u3, ha, hb)
    }
#undef ACCROW

    // write squared A to warp-private smem
    float* sA = smA[warp];
#pragma unroll
    for (int n = 0; n < 4; n++)
#pragma unroll
        for (int cc = 0; cc < 8; cc++) {
            float a = acc[n][cc];
            sA[(jg * 4 + n) * 17 + 4 * ch2 + cc] = a * a;
        }
    __syncwarp();

    float inv[8];
#pragma unroll
    for (int q = 0; q < 8; q++) {
        int idx = lane * 8 + q;
        int li = idx >> 6, ni = (idx >> 4) & 3, ci = idx & 15;
        int base = li * li;
        float sacc = 0.f;
        for (int m = 0; m <= 2 * li; m++)
            sacc += sA[((base + m) * 4 + ni) * 17 + ci];
        inv[q] = sacc * rsqrtf(2.0f * (float)li + 1.0f);
    }

    if (FINAL) {
        float part = 0.f;
#pragma unroll
        for (int q = 0; q < 8; q++)
            part = fmaf(inv[q], w_out[lane * 8 + q], part);
#pragma unroll
        for (int o = 16; o > 0; o >>= 1)
            part += __shfl_down_sync(0xFFFFFFFFu, part, o);
        if (lane == 0)
            atomicAdd(&out[sid[atom]], part + comp_w[species[atom]]);
    } else {
        float* sv = sminv[warp];
#pragma unroll
        for (int q = 0; q < 8; q++) sv[lane * 8 + q] = inv[q];
        __syncwarp();
        int cp = lane & 15, half = lane >> 4;
        float p0 = 0.f, p1 = 0.f;
#pragma unroll 8
        for (int i = 0; i < 128; i += 2) {
            int jj = (half << 7) + i;
            p0 = fmaf(sv[jj],     W[jj * 16 + cp],       p0);
            p1 = fmaf(sv[jj + 1], W[(jj + 1) * 16 + cp], p1);
        }
        float p = p0 + p1;
        p += __shfl_down_sync(0xFFFFFFFFu, p, 16);
        if (lane < 16)
            g_h1[atom * CH + lane] = p * g_cemb[atom * CH + lane];
    }
}

// ---------------- launch ----------------
extern "C" void kernel_launch(void* const* d_in, const int* in_sizes, int n_in,
                              void* d_out, int out_size) {
    const float* positions  = (const float*)d_in[0];
    const float* embed      = (const float*)d_in[1];
    const float* W_rad      = (const float*)d_in[2];
    const float* W_inv1     = (const float*)d_in[3];
    // d_in[4] = W_inv2 is dead: reference returns inv2 before applying it
    const float* w_out      = (const float*)d_in[5];
    const float* comp_w     = (const float*)d_in[6];
    const int*   senders    = (const int*)d_in[7];
    const int*   receivers  = (const int*)d_in[8];
    const int*   species    = (const int*)d_in[9];
    const int*   struct_ids = (const int*)d_in[10];
    float* out = (float*)d_out;

    k_init<<<(N_ATOMS * CH + 255) / 256, 256>>>(embed, species, out);
    k_hist<<<(N_EDGES + 255) / 256, 256>>>(receivers);
    k_scan<<<1, 1024>>>();
    k_edges<<<(N_EDGES + 255) / 256, 256>>>(positions, senders, receivers, W_rad);

    k_layer<false><<<N_ATOMS / 4, 128>>>(0, W_inv1, nullptr, nullptr, nullptr, nullptr, nullptr);
    k_layer<true><<<N_ATOMS / 4, 128>>>(1, nullptr, w_out, comp_w, species, struct_ids, out);
}